// round 9
// baseline (speedup 1.0000x reference)
#include <cuda_runtime.h>
#include <cuda_bf16.h>
#include <cstdint>

#define BATCH 4096
#define BB    8192      // both branches concatenated
#define FDIM  58
#define TT    30
#define H1    512
#define H2    128
#define H3    64

// ---------------- static device scratch ----------------
__device__ __nv_bfloat16 g_Xh [(size_t)BB*TT*64];
__device__ __nv_bfloat16 g_Xl [(size_t)BB*TT*64];
__device__ __nv_bfloat16 g_S1h[(size_t)BB*TT*H1];
__device__ __nv_bfloat16 g_S1l[(size_t)BB*TT*H1];
__device__ __nv_bfloat16 g_S2h[(size_t)BB*TT*H2];
__device__ __nv_bfloat16 g_S2l[(size_t)BB*TT*H2];
__device__ float         g_H3seq[(size_t)BB*TT*H3];
__device__ __nv_bfloat16 g_HAh[(size_t)BB*H1], g_HAl[(size_t)BB*H1];
__device__ __nv_bfloat16 g_HBh[(size_t)BB*H1], g_HBl[(size_t)BB*H1];
__device__ float         g_C  [(size_t)BB*H1];
__device__ __nv_bfloat16 g_W1h[2048*576], g_W1l[2048*576];   // [n=h*4+g][k]
__device__ __nv_bfloat16 g_W2h[512*640],  g_W2l[512*640];
__device__ __nv_bfloat16 g_W3h[256*192],  g_W3l[256*192];
__device__ float g_b1p[2048], g_b2p[512], g_b3p[256];
__device__ float g_Wf1p[1920*960], g_Wf2p[960*480];
__device__ float g_D [(size_t)BATCH*1920];
__device__ float g_F1[(size_t)BATCH*960];
__device__ float g_F2[(size_t)BATCH*480];

// ---------------- helpers ----------------
__device__ __forceinline__ uint32_t smem_u32(const void* p) {
    uint32_t a;
    asm("{ .reg .u64 t; cvta.to.shared.u64 t, %1; cvt.u32.u64 %0, t; }" : "=r"(a) : "l"(p));
    return a;
}

__device__ __forceinline__ float tanha(float x) {
    float y;
    asm("tanh.approx.f32 %0, %1;" : "=f"(y) : "f"(x));
    return y;
}
__device__ __forceinline__ float sigm(float x) { return fmaf(tanha(x*0.5f), 0.5f, 0.5f); }

#define LDSM_X4(r0, r1, r2, r3, a) \
    asm volatile("ldmatrix.sync.aligned.m8n8.x4.shared.b16 {%0,%1,%2,%3}, [%4];" \
        : "=r"(r0), "=r"(r1), "=r"(r2), "=r"(r3) : "r"(a))

#define MMA_BF16(c, a, b) \
    asm volatile("mma.sync.aligned.m16n8k16.row.col.f32.bf16.bf16.f32 " \
        "{%0,%1,%2,%3}, {%4,%5,%6,%7}, {%8,%9}, {%0,%1,%2,%3};" \
        : "+f"((c)[0]), "+f"((c)[1]), "+f"((c)[2]), "+f"((c)[3]) \
        : "r"((a)[0]), "r"((a)[1]), "r"((a)[2]), "r"((a)[3]), "r"((b)[0]), "r"((b)[1]))

// ---------------- packing ----------------
__global__ void pack_x_hilo(const float* __restrict__ x1, const float* __restrict__ x2)
{
    int idx = blockIdx.x*blockDim.x + threadIdx.x;
    if (idx >= BB*TT*64) return;
    int k   = idx & 63;
    int tmp = idx >> 6;
    int t   = tmp % TT;
    int bb  = tmp / TT;
    const float* src = (bb < BATCH) ? x1 : x2;
    int bs = (bb < BATCH) ? bb : bb - BATCH;
    float v = (k < FDIM) ? src[((size_t)bs*FDIM + k)*TT + t] : 0.f;
    __nv_bfloat16 hi = __float2bfloat16(v);
    g_Xh[idx] = hi;
    g_Xl[idx] = __float2bfloat16(v - __bfloat162float(hi));
}

// weights: [n = h*4+gate][k], k<H: Whh, k>=H: Wih (zero-padded), split hi/lo.
// Destinations selected INSIDE device code (never pass __device__ globals as
// kernel args from host — that passes the host shadow symbol!).
template<int LAYER>
__global__ void pack_wb(const float* __restrict__ Wih, const float* __restrict__ Whh)
{
    constexpr int H   = (LAYER == 1) ? H1 : (LAYER == 2) ? H2 : H3;
    constexpr int INR = (LAYER == 1) ? FDIM : (LAYER == 2) ? H1 : H2;
    constexpr int IN  = (LAYER == 1) ? 64 : (LAYER == 2) ? H1 : H2;
    constexpr int KT  = H + IN;
    __nv_bfloat16* Wh;
    __nv_bfloat16* Wl;
    if constexpr (LAYER == 1)      { Wh = g_W1h; Wl = g_W1l; }
    else if constexpr (LAYER == 2) { Wh = g_W2h; Wl = g_W2l; }
    else                           { Wh = g_W3h; Wl = g_W3l; }

    int idx = blockIdx.x*blockDim.x + threadIdx.x;
    if (idx >= 4*H*KT) return;
    int n = idx / KT, k = idx % KT;
    int h = n >> 2, g = n & 3;
    float v;
    if (k < H) v = Whh[(size_t)(g*H + h)*H + k];
    else {
        int kk = k - H;
        v = (kk < INR) ? Wih[(size_t)(g*H + h)*INR + kk] : 0.f;
    }
    __nv_bfloat16 hi = __float2bfloat16(v);
    Wh[idx] = hi;
    Wl[idx] = __float2bfloat16(v - __bfloat162float(hi));
}

__global__ void pack_bias(const float* __restrict__ b1, const float* __restrict__ b2,
                          const float* __restrict__ b3)
{
    int i = blockIdx.x*blockDim.x + threadIdx.x;
    if (i < 2048) {
        int h = i >> 2, g = i & 3;
        g_b1p[i] = b1[g*H1 + h];
    } else if (i < 2048 + 512) {
        int c = i - 2048, h = c >> 2, g = c & 3;
        g_b2p[c] = b2[g*H2 + h];
    } else if (i < 2048 + 512 + 256) {
        int c = i - 2560, h = c >> 2, g = c & 3;
        g_b3p[c] = b3[g*H3 + h];
    }
}

__global__ void pack_wf1(const float* __restrict__ Wf1)
{
    int idx = blockIdx.x*blockDim.x + threadIdx.x;
    if (idx >= 1920*960) return;
    int k = idx / 960, n = idx % 960;
    g_Wf1p[idx] = Wf1[(size_t)n*1920 + k];
}

__global__ void pack_wf2(const float* __restrict__ Wf2)
{
    int idx = blockIdx.x*blockDim.x + threadIdx.x;
    if (idx >= 960*480) return;
    int k = idx / 480, n = idx % 480;
    g_Wf2p[idx] = Wf2[(size_t)n*960 + k];
}

__global__ void zero_state()
{
    int i = blockIdx.x*blockDim.x + threadIdx.x;
    if (i < BB*H1) {
        g_HAh[i] = __float2bfloat16(0.f);
        g_HAl[i] = __float2bfloat16(0.f);
        g_C[i]   = 0.f;
    }
}

// ---------------- fused mma.sync LSTM step (kpair smem + ldmatrix) ----------------
// D[128x128] = [Hprev ; x_t] x W^T (bf16 hi/lo, 3 products), then LSTM cell.
// 256 threads = 8 warps (2 M x 4 N), warp tile 64x32, K chunks of 32.
// smem tiles: uint32 kpair words [row][kp], stride 20 (conflict-free), 40 KB.
// Fragments loaded with ldmatrix.x4 (addresses reproduce the proven scalar map).
template<int H, int IN, int LAYER>
__global__ __launch_bounds__(256, 2) void lstm_step(int t)
{
    constexpr int KT  = H + IN;
    constexpr int NCH = KT / 32;

    __shared__ __align__(16) uint32_t sAh[128][20];
    __shared__ __align__(16) uint32_t sAl[128][20];
    __shared__ __align__(16) uint32_t sBh[128][20];
    __shared__ __align__(16) uint32_t sBl[128][20];

    const int tid  = threadIdx.x;
    const int wid  = tid >> 5;
    const int lane = tid & 31;
    const int m0   = blockIdx.x * 128;
    const int n0   = blockIdx.y * 128;
    const int wm   = (wid & 1) * 64;    // warp m offset (2 warps in M)
    const int wn   = (wid >> 1) * 32;   // warp n offset (4 warps in N)
    const int g    = lane >> 2;         // group id 0..7 (epilogue)
    const int tig  = lane & 3;          // thread in group (epilogue)

    // ldmatrix lane mapping: quad q supplies matrix q's 8 row addresses.
    // m0=(rows+0..7, kp+0..3) m1=(rows+8..15, kp+0..3) m2=(rows+0..7, kp+4..7) m3=(rows+8..15, kp+4..7)
    const int lr     = lane & 7;
    const int quad   = lane >> 3;
    const int rowAdd = (quad & 1) * 8 + lr;
    const int kpAdd  = (quad >> 1) * 4;

    const uint32_t aBaseH = smem_u32(sAh);
    const uint32_t aBaseL = smem_u32(sAl);
    const uint32_t bBaseH = smem_u32(sBh);
    const uint32_t bBaseL = smem_u32(sBl);

    const __nv_bfloat16 *Hph, *Hpl, *Xh, *Xl, *Wh, *Wl;
    const float* bp;
    __nv_bfloat16 *Hnh, *Hnl, *Sh = nullptr, *Sl = nullptr;
    if constexpr (LAYER == 1) { Xh = g_Xh;  Xl = g_Xl;  Wh = g_W1h; Wl = g_W1l; bp = g_b1p; Sh = g_S1h; Sl = g_S1l; }
    else if constexpr (LAYER == 2) { Xh = g_S1h; Xl = g_S1l; Wh = g_W2h; Wl = g_W2l; bp = g_b2p; Sh = g_S2h; Sl = g_S2l; }
    else { Xh = g_S2h; Xl = g_S2l; Wh = g_W3h; Wl = g_W3l; bp = g_b3p; }
    Hph = (t & 1) ? g_HBh : g_HAh;
    Hpl = (t & 1) ? g_HBl : g_HAl;
    Hnh = (t & 1) ? g_HAh : g_HBh;
    Hnl = (t & 1) ? g_HAl : g_HBl;

    float acc[4][4][4];
    #pragma unroll
    for (int i = 0; i < 4; i++)
        #pragma unroll
        for (int j = 0; j < 4; j++)
            #pragma unroll
            for (int k = 0; k < 4; k++) acc[i][j][k] = 0.f;

    for (int ch = 0; ch < NCH; ch++) {
        const int k0 = ch * 32;
        const bool st = (k0 < H);        // chunk entirely in state (H multiple of 32)

        // ---- fill: 4 tiles x 128 rows x 32 bf16 (= 2 uint4 per row) ----
        #pragma unroll
        for (int tl = 0; tl < 4; tl++) {
            #pragma unroll
            for (int p = 0; p < 2; p++) {
                int u = tid + p*256;      // 0..511
                int r = u >> 2;           // 0..127
                int q = u & 3;            // 16B quarter (4 kpairs)
                const __nv_bfloat16* src;
                if (tl == 0)      src = st ? (Hph + (size_t)(m0 + r)*H + k0)
                                           : (Xh + ((size_t)(m0 + r)*TT + t)*IN + (k0 - H));
                else if (tl == 1) src = st ? (Hpl + (size_t)(m0 + r)*H + k0)
                                           : (Xl + ((size_t)(m0 + r)*TT + t)*IN + (k0 - H));
                else if (tl == 2) src = Wh + (size_t)(n0 + r)*KT + k0;
                else              src = Wl + (size_t)(n0 + r)*KT + k0;
                uint4 v = reinterpret_cast<const uint4*>(src)[q];
                uint32_t (*dst)[20] = (tl == 0) ? sAh : (tl == 1) ? sAl : (tl == 2) ? sBh : sBl;
                *reinterpret_cast<uint4*>(&dst[r][q*4]) = v;
            }
        }
        __syncthreads();

        // ---- two k16 mma steps ----
        #pragma unroll
        for (int s = 0; s < 2; s++) {
            const int kb = s * 8;
            const uint32_t loff = (uint32_t)((kb + kpAdd) * 4);
            uint32_t Bh_[4][2], Bl_[4][2];
            #pragma unroll
            for (int jj = 0; jj < 2; jj++) {
                uint32_t roff = (uint32_t)((wn + jj*16 + rowAdd) * 80) + loff;  // *20 words *4 B
                uint32_t h0, h1, h2, h3, l0, l1, l2, l3;
                LDSM_X4(h0, h1, h2, h3, bBaseH + roff);
                LDSM_X4(l0, l1, l2, l3, bBaseL + roff);
                Bh_[jj*2][0]   = h0; Bh_[jj*2][1]   = h2;
                Bh_[jj*2+1][0] = h1; Bh_[jj*2+1][1] = h3;
                Bl_[jj*2][0]   = l0; Bl_[jj*2][1]   = l2;
                Bl_[jj*2+1][0] = l1; Bl_[jj*2+1][1] = l3;
            }
            #pragma unroll
            for (int i = 0; i < 4; i++) {
                uint32_t roff = (uint32_t)((wm + i*16 + rowAdd) * 80) + loff;
                uint32_t Ah_[4], Al_[4];
                LDSM_X4(Ah_[0], Ah_[1], Ah_[2], Ah_[3], aBaseH + roff);
                LDSM_X4(Al_[0], Al_[1], Al_[2], Al_[3], aBaseL + roff);
                #pragma unroll
                for (int j = 0; j < 4; j++) {
                    MMA_BF16(acc[i][j], Ah_, Bh_[j]);
                    MMA_BF16(acc[i][j], Ah_, Bl_[j]);
                    MMA_BF16(acc[i][j], Al_, Bh_[j]);
                }
            }
        }
        __syncthreads();
    }

    // ---- epilogue: shuffle-assemble gate quadruples, LSTM cell ----
    #pragma unroll
    for (int i = 0; i < 4; i++) {
        #pragma unroll
        for (int j = 0; j < 4; j++) {
            float c0 = acc[i][j][0], c1 = acc[i][j][1];
            float c2 = acc[i][j][2], c3 = acc[i][j][3];
            float s0 = __shfl_xor_sync(0xffffffffu, c0, 1);
            float s1 = __shfl_xor_sync(0xffffffffu, c1, 1);
            float s2 = __shfl_xor_sync(0xffffffffu, c2, 1);
            float s3 = __shfl_xor_sync(0xffffffffu, c3, 1);
            int row, nb;
            float g0, g1, g2, g3;
            if (!(lane & 1)) { row = wm + i*16 + g;     nb = wn + j*8 + tig*2;     g0 = c0; g1 = c1; g2 = s0; g3 = s1; }
            else             { row = wm + i*16 + g + 8; nb = wn + j*8 + tig*2 - 2; g0 = s2; g1 = s3; g2 = c2; g3 = c3; }

            const size_t m = (size_t)(m0 + row);
            const int n  = n0 + nb;            // column of gate i (n % 4 == 0)
            const int jh = n >> 2;             // h column
            float gi = g0 + bp[n + 0];
            float gf = g1 + bp[n + 1];
            float gg = g2 + bp[n + 2];
            float go = g3 + bp[n + 3];
            float iv = sigm(gi);
            float fv = sigm(gf);
            float gv = tanha(gg);
            float ov = sigm(go);
            float c  = fv * g_C[m*H + jh] + iv * gv;
            g_C[m*H + jh] = c;
            float h  = ov * tanha(c);
            __nv_bfloat16 hh = __float2bfloat16(h);
            Hnh[m*H + jh] = hh;
            Hnl[m*H + jh] = __float2bfloat16(h - __bfloat162float(hh));
            float rh = fmaxf(h, 0.f);
            if constexpr (LAYER == 3) {
                g_H3seq[(m*TT + t)*H3 + jh] = rh;
            } else {
                __nv_bfloat16 rhh = __float2bfloat16(rh);
                Sh[(m*TT + t)*H + jh] = rhh;
                Sl[(m*TT + t)*H + jh] = __float2bfloat16(rh - __bfloat162float(rhh));
            }
        }
    }
}

// ---------------- guarded SGEMM + bias + relu for FC layers (proven) ----------------
template<int ID>
__global__ __launch_bounds__(256) void fc_gemm(const float* __restrict__ bias,
                                               int M, int N, int K)
{
    const float* __restrict__ A;
    const float* __restrict__ Bw;
    float*       __restrict__ Co;
    if constexpr (ID == 1) { A = g_D;  Bw = g_Wf1p; Co = g_F1; }
    else                   { A = g_F1; Bw = g_Wf2p; Co = g_F2; }

    __shared__ float As[16][132];
    __shared__ float Bs[16][128];

    const int m0  = blockIdx.x * 128;
    const int n0  = blockIdx.y * 128;
    const int tid = threadIdx.x;
    const int tx  = tid & 15;
    const int ty  = tid >> 4;

    float acc[8][8];
    #pragma unroll
    for (int i = 0; i < 8; i++)
        #pragma unroll
        for (int j = 0; j < 8; j++) acc[i][j] = 0.f;

    const int kl = tid & 15;
    const int ml = tid >> 4;
    const int bn = tid & 127;
    const int bk = (tid >> 7) * 8;

    for (int k0 = 0; k0 < K; k0 += 16) {
        const int kA = k0 + kl;
        #pragma unroll
        for (int i = 0; i < 8; i++) {
            int m = m0 + ml + 16*i;
            As[kl][ml + 16*i] = (kA < K) ? A[(size_t)m*K + kA] : 0.f;
        }
        const int n = n0 + bn;
        #pragma unroll
        for (int i = 0; i < 8; i++) {
            int k = k0 + bk + i;
            Bs[bk + i][bn] = (k < K && n < N) ? Bw[(size_t)k*N + n] : 0.f;
        }
        __syncthreads();
        #pragma unroll
        for (int kk = 0; kk < 16; kk++) {
            float a[8], b[8];
            #pragma unroll
            for (int i = 0; i < 8; i++) a[i] = As[kk][ty*8 + i];
            #pragma unroll
            for (int j = 0; j < 8; j++) b[j] = Bs[kk][tx*8 + j];
            #pragma unroll
            for (int i = 0; i < 8; i++)
                #pragma unroll
                for (int j = 0; j < 8; j++) acc[i][j] += a[i]*b[j];
        }
        __syncthreads();
    }

    #pragma unroll
    for (int i = 0; i < 8; i++) {
        const int m = m0 + ty*8 + i;
        #pragma unroll
        for (int j = 0; j < 8; j++) {
            const int n = n0 + tx*8 + j;
            if (n < N)
                Co[(size_t)m*N + n] = fmaxf(acc[i][j] + bias[n], 0.f);
        }
    }
}

// ---------------- |h1 - h2| ----------------
__global__ void diff_kernel()
{
    int idx = blockIdx.x*blockDim.x + threadIdx.x;
    if (idx >= BATCH*1920) return;
    int b = idx / 1920;
    int r = idx % 1920;
    int t = r / 64, h = r % 64;
    float a = g_H3seq[((size_t)b*TT + t)*64 + h];
    float c = g_H3seq[((size_t)(b + BATCH)*TT + t)*64 + h];
    g_D[idx] = fabsf(a - c);
}

// ---------------- fused FC3 + FC4 head ----------------
__global__ __launch_bounds__(256) void head_kernel(const float* __restrict__ Wf3,
                                                   const float* __restrict__ bf3,
                                                   const float* __restrict__ Wf4,
                                                   const float* __restrict__ bf4,
                                                   float* __restrict__ out)
{
    __shared__ float w3[16*480];
    __shared__ float w4[16];
    __shared__ float b3s[16];
    for (int i = threadIdx.x; i < 16*480; i += blockDim.x) w3[i] = Wf3[i];
    if (threadIdx.x < 16) { w4[threadIdx.x] = Wf4[threadIdx.x]; b3s[threadIdx.x] = bf3[threadIdx.x]; }
    __syncthreads();

    int b = blockIdx.x*blockDim.x + threadIdx.x;
    if (b >= BATCH) return;

    float acc[16];
    #pragma unroll
    for (int j = 0; j < 16; j++) acc[j] = b3s[j];

    const float* __restrict__ row = g_F2 + (size_t)b*480;
    for (int k = 0; k < 480; k++) {
        float v = row[k];
        #pragma unroll
        for (int j = 0; j < 16; j++) acc[j] += v * w3[j*480 + k];
    }
    float o = bf4[0];
    #pragma unroll
    for (int j = 0; j < 16; j++) o += fmaxf(acc[j], 0.f) * w4[j];
    out[b] = o;
}

// ---------------- launch ----------------
extern "C" void kernel_launch(void* const* d_in, const int* in_sizes, int n_in,
                              void* d_out, int out_size)
{
    const float* x1   = (const float*)d_in[0];
    const float* x2   = (const float*)d_in[1];
    const float* Wih1 = (const float*)d_in[2];
    const float* Whh1 = (const float*)d_in[3];
    const float* b1   = (const float*)d_in[4];
    const float* Wih2 = (const float*)d_in[5];
    const float* Whh2 = (const float*)d_in[6];
    const float* b2   = (const float*)d_in[7];
    const float* Wih3 = (const float*)d_in[8];
    const float* Whh3 = (const float*)d_in[9];
    const float* b3   = (const float*)d_in[10];
    const float* Wf1  = (const float*)d_in[11];
    const float* bf1  = (const float*)d_in[12];
    const float* Wf2  = (const float*)d_in[13];
    const float* bf2  = (const float*)d_in[14];
    const float* Wf3  = (const float*)d_in[15];
    const float* bf3  = (const float*)d_in[16];
    const float* Wf4  = (const float*)d_in[17];
    const float* bf4  = (const float*)d_in[18];
    float* out = (float*)d_out;

    pack_x_hilo<<<(BB*TT*64 + 255)/256, 256>>>(x1, x2);
    pack_wb<1><<<(2048*576 + 255)/256, 256>>>(Wih1, Whh1);
    pack_wb<2><<<(512*640  + 255)/256, 256>>>(Wih2, Whh2);
    pack_wb<3><<<(256*192  + 255)/256, 256>>>(Wih3, Whh3);
    pack_bias<<<(2816 + 255)/256, 256>>>(b1, b2, b3);
    pack_wf1<<<(1920*960 + 255)/256, 256>>>(Wf1);
    pack_wf2<<<(960*480  + 255)/256, 256>>>(Wf2);

    // layer 1: 58 -> 512   (KT = 576)
    zero_state<<<(BB*H1 + 255)/256, 256>>>();
    for (int t = 0; t < TT; t++)
        lstm_step<H1, 64, 1><<<dim3(BB/128, (4*H1)/128), 256>>>(t);

    // layer 2: 512 -> 128  (KT = 640)
    zero_state<<<(BB*H1 + 255)/256, 256>>>();
    for (int t = 0; t < TT; t++)
        lstm_step<H2, H1, 2><<<dim3(BB/128, (4*H2)/128), 256>>>(t);

    // layer 3: 128 -> 64   (KT = 192)
    zero_state<<<(BB*H1 + 255)/256, 256>>>();
    for (int t = 0; t < TT; t++)
        lstm_step<H3, H2, 3><<<dim3(BB/128, (4*H3)/128), 256>>>(t);

    diff_kernel<<<(BATCH*1920 + 255)/256, 256>>>();

    fc_gemm<1><<<dim3(BATCH/128, (960 + 127)/128), 256>>>(bf1, BATCH, 960, 1920);
    fc_gemm<2><<<dim3(BATCH/128, (480 + 127)/128), 256>>>(bf2, BATCH, 480, 960);
    head_kernel<<<(BATCH + 255)/256, 256>>>(Wf3, bf3, Wf4, bf4, out);
}

// round 12
// speedup vs baseline: 1.1893x; 1.1893x over previous
#include <cuda_runtime.h>
#include <cuda_bf16.h>
#include <cstdint>

#define BATCH 4096
#define BB    8192      // both branches concatenated
#define FDIM  58
#define TT    30
#define H1    512
#define H2    128
#define H3    64

// ---------------- static device scratch ----------------
__device__ __nv_bfloat16 g_Xh [(size_t)BB*TT*64];
__device__ __nv_bfloat16 g_Xl [(size_t)BB*TT*64];
__device__ __nv_bfloat16 g_S1h[(size_t)BB*TT*H1];
__device__ __nv_bfloat16 g_S1l[(size_t)BB*TT*H1];
__device__ __nv_bfloat16 g_S2h[(size_t)BB*TT*H2];
__device__ __nv_bfloat16 g_S2l[(size_t)BB*TT*H2];
__device__ float         g_H3seq[(size_t)BB*TT*H3];
__device__ __nv_bfloat16 g_HAh[(size_t)BB*H1], g_HAl[(size_t)BB*H1];
__device__ __nv_bfloat16 g_HBh[(size_t)BB*H1], g_HBl[(size_t)BB*H1];
__device__ float         g_C  [(size_t)BB*H1];
__device__ __nv_bfloat16 g_W1h[2048*576], g_W1l[2048*576];   // [n=h*4+g][k]
__device__ __nv_bfloat16 g_W2h[512*640],  g_W2l[512*640];
__device__ __nv_bfloat16 g_W3h[256*192],  g_W3l[256*192];
__device__ float g_b1p[2048], g_b2p[512], g_b3p[256];
__device__ float g_Wf1p[1920*960], g_Wf2p[960*480];
__device__ float g_D [(size_t)BATCH*1920];
__device__ float g_F1[(size_t)BATCH*960];
__device__ float g_F2[(size_t)BATCH*480];

// ---------------- helpers ----------------
__device__ __forceinline__ uint32_t smem_u32(const void* p) {
    uint32_t a;
    asm("{ .reg .u64 t; cvta.to.shared.u64 t, %1; cvt.u32.u64 %0, t; }" : "=r"(a) : "l"(p));
    return a;
}

__device__ __forceinline__ float tanha(float x) {
    float y;
    asm("tanh.approx.f32 %0, %1;" : "=f"(y) : "f"(x));
    return y;
}
__device__ __forceinline__ float sigm(float x) { return fmaf(tanha(x*0.5f), 0.5f, 0.5f); }

#define CP_ASYNC16(sm, gp) \
    asm volatile("cp.async.cg.shared.global [%0], [%1], 16;" :: "r"(sm), "l"(gp) : "memory")
#define CP_COMMIT() asm volatile("cp.async.commit_group;" ::: "memory")
#define CP_WAIT0()  asm volatile("cp.async.wait_group 0;" ::: "memory")

#define MMA_BF16(c, a, b) \
    asm volatile("mma.sync.aligned.m16n8k16.row.col.f32.bf16.bf16.f32 " \
        "{%0,%1,%2,%3}, {%4,%5,%6,%7}, {%8,%9}, {%0,%1,%2,%3};" \
        : "+f"((c)[0]), "+f"((c)[1]), "+f"((c)[2]), "+f"((c)[3]) \
        : "r"((a)[0]), "r"((a)[1]), "r"((a)[2]), "r"((a)[3]), "r"((b)[0]), "r"((b)[1]))

// ---------------- packing ----------------
__global__ void pack_x_hilo(const float* __restrict__ x1, const float* __restrict__ x2)
{
    int idx = blockIdx.x*blockDim.x + threadIdx.x;
    if (idx >= BB*TT*64) return;
    int k   = idx & 63;
    int tmp = idx >> 6;
    int t   = tmp % TT;
    int bb  = tmp / TT;
    const float* src = (bb < BATCH) ? x1 : x2;
    int bs = (bb < BATCH) ? bb : bb - BATCH;
    float v = (k < FDIM) ? src[((size_t)bs*FDIM + k)*TT + t] : 0.f;
    __nv_bfloat16 hi = __float2bfloat16(v);
    g_Xh[idx] = hi;
    g_Xl[idx] = __float2bfloat16(v - __bfloat162float(hi));
}

// weights: [n = h*4+gate][k], k<H: Whh, k>=H: Wih (zero-padded), split hi/lo.
// Destinations selected INSIDE device code (never pass __device__ globals as
// kernel args from host — that passes the host shadow symbol!).
template<int LAYER>
__global__ void pack_wb(const float* __restrict__ Wih, const float* __restrict__ Whh)
{
    constexpr int H   = (LAYER == 1) ? H1 : (LAYER == 2) ? H2 : H3;
    constexpr int INR = (LAYER == 1) ? FDIM : (LAYER == 2) ? H1 : H2;
    constexpr int IN  = (LAYER == 1) ? 64 : (LAYER == 2) ? H1 : H2;
    constexpr int KT  = H + IN;
    __nv_bfloat16* Wh;
    __nv_bfloat16* Wl;
    if constexpr (LAYER == 1)      { Wh = g_W1h; Wl = g_W1l; }
    else if constexpr (LAYER == 2) { Wh = g_W2h; Wl = g_W2l; }
    else                           { Wh = g_W3h; Wl = g_W3l; }

    int idx = blockIdx.x*blockDim.x + threadIdx.x;
    if (idx >= 4*H*KT) return;
    int n = idx / KT, k = idx % KT;
    int h = n >> 2, g = n & 3;
    float v;
    if (k < H) v = Whh[(size_t)(g*H + h)*H + k];
    else {
        int kk = k - H;
        v = (kk < INR) ? Wih[(size_t)(g*H + h)*INR + kk] : 0.f;
    }
    __nv_bfloat16 hi = __float2bfloat16(v);
    Wh[idx] = hi;
    Wl[idx] = __float2bfloat16(v - __bfloat162float(hi));
}

__global__ void pack_bias(const float* __restrict__ b1, const float* __restrict__ b2,
                          const float* __restrict__ b3)
{
    int i = blockIdx.x*blockDim.x + threadIdx.x;
    if (i < 2048) {
        int h = i >> 2, g = i & 3;
        g_b1p[i] = b1[g*H1 + h];
    } else if (i < 2048 + 512) {
        int c = i - 2048, h = c >> 2, g = c & 3;
        g_b2p[c] = b2[g*H2 + h];
    } else if (i < 2048 + 512 + 256) {
        int c = i - 2560, h = c >> 2, g = c & 3;
        g_b3p[c] = b3[g*H3 + h];
    }
}

__global__ void pack_wf1(const float* __restrict__ Wf1)
{
    int idx = blockIdx.x*blockDim.x + threadIdx.x;
    if (idx >= 1920*960) return;
    int k = idx / 960, n = idx % 960;
    g_Wf1p[idx] = Wf1[(size_t)n*1920 + k];
}

__global__ void pack_wf2(const float* __restrict__ Wf2)
{
    int idx = blockIdx.x*blockDim.x + threadIdx.x;
    if (idx >= 960*480) return;
    int k = idx / 480, n = idx % 480;
    g_Wf2p[idx] = Wf2[(size_t)n*960 + k];
}

__global__ void zero_state()
{
    int i = blockIdx.x*blockDim.x + threadIdx.x;
    if (i < BB*H1) {
        g_HAh[i] = __float2bfloat16(0.f);
        g_HAl[i] = __float2bfloat16(0.f);
        g_C[i]   = 0.f;
    }
}

// ---------------- fused mma.sync LSTM step (kpair smem, cp.async 2-stage) ----------------
// D[128x128] = [Hprev ; x_t] x W^T (bf16 hi/lo, 3 products), then LSTM cell.
// 256 threads = 8 warps (2 M x 4 N), warp tile 64x32, K chunks of 32.
// smem: 2 stages x 4 tiles x [128][20] uint32 kpair words = 80 KB dynamic.
// Pipeline: wait(ch) -> sync -> cp.async fill(ch+1) -> mma(ch)  (fill overlaps mma).
template<int H, int IN, int LAYER>
__global__ __launch_bounds__(256, 2) void lstm_step(int t)
{
    constexpr int KT  = H + IN;
    constexpr int NCH = KT / 32;
    constexpr int TILE_W = 2560;    // words per tile (128*20)
    constexpr int STAGE_W = 10240;  // words per stage (4 tiles)

    extern __shared__ __align__(16) uint32_t dsm[];

    const int tid  = threadIdx.x;
    const int wid  = tid >> 5;
    const int lane = tid & 31;
    const int m0   = blockIdx.x * 128;
    const int n0   = blockIdx.y * 128;
    const int wm   = (wid & 1) * 64;    // warp m offset (2 warps in M)
    const int wn   = (wid >> 1) * 32;   // warp n offset (4 warps in N)
    const int g    = lane >> 2;         // group id 0..7
    const int tig  = lane & 3;          // thread in group

    const __nv_bfloat16 *Hph, *Hpl, *Xh, *Xl, *Wh, *Wl;
    const float* bp;
    __nv_bfloat16 *Hnh, *Hnl, *Sh = nullptr, *Sl = nullptr;
    if constexpr (LAYER == 1) { Xh = g_Xh;  Xl = g_Xl;  Wh = g_W1h; Wl = g_W1l; bp = g_b1p; Sh = g_S1h; Sl = g_S1l; }
    else if constexpr (LAYER == 2) { Xh = g_S1h; Xl = g_S1l; Wh = g_W2h; Wl = g_W2l; bp = g_b2p; Sh = g_S2h; Sl = g_S2l; }
    else { Xh = g_S2h; Xl = g_S2l; Wh = g_W3h; Wl = g_W3l; bp = g_b3p; }
    Hph = (t & 1) ? g_HBh : g_HAh;
    Hpl = (t & 1) ? g_HBl : g_HAl;
    Hnh = (t & 1) ? g_HAh : g_HBh;
    Hnl = (t & 1) ? g_HAl : g_HBl;

    // per-thread fill coordinates (2 transfers per tile)
    const int fr0 = tid >> 2;            // row for p=0
    const int fq0 = tid & 3;             // quarter for p=0
    const int fr1 = (tid + 256) >> 2;    // row for p=1
    const int fq1 = (tid + 256) & 3;

    // cp.async fill of chunk ch into stage buffer
    auto fill = [&](int ch, int stage) {
        const int k0 = ch * 32;
        const bool st = (k0 < H);
        uint32_t* sb = dsm + stage * STAGE_W;
        #pragma unroll
        for (int tl = 0; tl < 4; tl++) {
            #pragma unroll
            for (int p = 0; p < 2; p++) {
                int r = p ? fr1 : fr0;
                int q = p ? fq1 : fq0;
                const __nv_bfloat16* src;
                if (tl == 0)      src = st ? (Hph + (size_t)(m0 + r)*H + k0)
                                           : (Xh + ((size_t)(m0 + r)*TT + t)*IN + (k0 - H));
                else if (tl == 1) src = st ? (Hpl + (size_t)(m0 + r)*H + k0)
                                           : (Xl + ((size_t)(m0 + r)*TT + t)*IN + (k0 - H));
                else if (tl == 2) src = Wh + (size_t)(n0 + r)*KT + k0;
                else              src = Wl + (size_t)(n0 + r)*KT + k0;
                uint32_t so = smem_u32(sb + tl*TILE_W + r*20 + q*4);
                CP_ASYNC16(so, src + q*8);
            }
        }
        CP_COMMIT();
    };

    float acc[4][4][4];
    #pragma unroll
    for (int i = 0; i < 4; i++)
        #pragma unroll
        for (int j = 0; j < 4; j++)
            #pragma unroll
            for (int k = 0; k < 4; k++) acc[i][j][k] = 0.f;

    fill(0, 0);

    for (int ch = 0; ch < NCH; ch++) {
        const int stage = ch & 1;
        CP_WAIT0();
        __syncthreads();
        if (ch + 1 < NCH) fill(ch + 1, (ch + 1) & 1);

        const uint32_t* sAh = dsm + stage*STAGE_W;
        const uint32_t* sAl = sAh + TILE_W;
        const uint32_t* sBh = sAl + TILE_W;
        const uint32_t* sBl = sBh + TILE_W;

        // ---- two k16 mma steps (proven scalar-LDS fragment map) ----
        #pragma unroll
        for (int s = 0; s < 2; s++) {
            const int kb = s * 8;
            uint32_t Bh_[4][2], Bl_[4][2];
            #pragma unroll
            for (int j = 0; j < 4; j++) {
                int col = wn + j*8 + g;
                Bh_[j][0] = sBh[col*20 + kb + tig];
                Bh_[j][1] = sBh[col*20 + kb + 4 + tig];
                Bl_[j][0] = sBl[col*20 + kb + tig];
                Bl_[j][1] = sBl[col*20 + kb + 4 + tig];
            }
            #pragma unroll
            for (int i = 0; i < 4; i++) {
                int row = wm + i*16 + g;
                uint32_t Ah_[4], Al_[4];
                Ah_[0] = sAh[row*20       + kb + tig];
                Ah_[1] = sAh[(row + 8)*20 + kb + tig];
                Ah_[2] = sAh[row*20       + kb + 4 + tig];
                Ah_[3] = sAh[(row + 8)*20 + kb + 4 + tig];
                Al_[0] = sAl[row*20       + kb + tig];
                Al_[1] = sAl[(row + 8)*20 + kb + tig];
                Al_[2] = sAl[row*20       + kb + 4 + tig];
                Al_[3] = sAl[(row + 8)*20 + kb + 4 + tig];
                #pragma unroll
                for (int j = 0; j < 4; j++) {
                    MMA_BF16(acc[i][j], Ah_, Bh_[j]);
                    MMA_BF16(acc[i][j], Ah_, Bl_[j]);
                    MMA_BF16(acc[i][j], Al_, Bh_[j]);
                }
            }
        }
        __syncthreads();
    }

    // ---- epilogue: shuffle-assemble gate quadruples, LSTM cell ----
    #pragma unroll
    for (int i = 0; i < 4; i++) {
        #pragma unroll
        for (int j = 0; j < 4; j++) {
            float c0 = acc[i][j][0], c1 = acc[i][j][1];
            float c2 = acc[i][j][2], c3 = acc[i][j][3];
            float s0 = __shfl_xor_sync(0xffffffffu, c0, 1);
            float s1 = __shfl_xor_sync(0xffffffffu, c1, 1);
            float s2 = __shfl_xor_sync(0xffffffffu, c2, 1);
            float s3 = __shfl_xor_sync(0xffffffffu, c3, 1);
            int row, nb;
            float g0, g1, g2, g3;
            if (!(lane & 1)) { row = wm + i*16 + g;     nb = wn + j*8 + tig*2;     g0 = c0; g1 = c1; g2 = s0; g3 = s1; }
            else             { row = wm + i*16 + g + 8; nb = wn + j*8 + tig*2 - 2; g0 = s2; g1 = s3; g2 = c2; g3 = c3; }

            const size_t m = (size_t)(m0 + row);
            const int n  = n0 + nb;            // column of gate i (n % 4 == 0)
            const int jh = n >> 2;             // h column
            float gi = g0 + bp[n + 0];
            float gf = g1 + bp[n + 1];
            float gg = g2 + bp[n + 2];
            float go = g3 + bp[n + 3];
            float iv = sigm(gi);
            float fv = sigm(gf);
            float gv = tanha(gg);
            float ov = sigm(go);
            float c  = fv * g_C[m*H + jh] + iv * gv;
            g_C[m*H + jh] = c;
            float h  = ov * tanha(c);
            __nv_bfloat16 hh = __float2bfloat16(h);
            Hnh[m*H + jh] = hh;
            Hnl[m*H + jh] = __float2bfloat16(h - __bfloat162float(hh));
            float rh = fmaxf(h, 0.f);
            if constexpr (LAYER == 3) {
                g_H3seq[(m*TT + t)*H3 + jh] = rh;
            } else {
                __nv_bfloat16 rhh = __float2bfloat16(rh);
                Sh[(m*TT + t)*H + jh] = rhh;
                Sl[(m*TT + t)*H + jh] = __float2bfloat16(rh - __bfloat162float(rhh));
            }
        }
    }
}

// ---------------- guarded SGEMM + bias + relu for FC layers (proven) ----------------
template<int ID>
__global__ __launch_bounds__(256) void fc_gemm(const float* __restrict__ bias,
                                               int M, int N, int K)
{
    const float* __restrict__ A;
    const float* __restrict__ Bw;
    float*       __restrict__ Co;
    if constexpr (ID == 1) { A = g_D;  Bw = g_Wf1p; Co = g_F1; }
    else                   { A = g_F1; Bw = g_Wf2p; Co = g_F2; }

    __shared__ float As[16][132];
    __shared__ float Bs[16][128];

    const int m0  = blockIdx.x * 128;
    const int n0  = blockIdx.y * 128;
    const int tid = threadIdx.x;
    const int tx  = tid & 15;
    const int ty  = tid >> 4;

    float acc[8][8];
    #pragma unroll
    for (int i = 0; i < 8; i++)
        #pragma unroll
        for (int j = 0; j < 8; j++) acc[i][j] = 0.f;

    const int kl = tid & 15;
    const int ml = tid >> 4;
    const int bn = tid & 127;
    const int bk = (tid >> 7) * 8;

    for (int k0 = 0; k0 < K; k0 += 16) {
        const int kA = k0 + kl;
        #pragma unroll
        for (int i = 0; i < 8; i++) {
            int m = m0 + ml + 16*i;
            As[kl][ml + 16*i] = (kA < K) ? A[(size_t)m*K + kA] : 0.f;
        }
        const int n = n0 + bn;
        #pragma unroll
        for (int i = 0; i < 8; i++) {
            int k = k0 + bk + i;
            Bs[bk + i][bn] = (k < K && n < N) ? Bw[(size_t)k*N + n] : 0.f;
        }
        __syncthreads();
        #pragma unroll
        for (int kk = 0; kk < 16; kk++) {
            float a[8], b[8];
            #pragma unroll
            for (int i = 0; i < 8; i++) a[i] = As[kk][ty*8 + i];
            #pragma unroll
            for (int j = 0; j < 8; j++) b[j] = Bs[kk][tx*8 + j];
            #pragma unroll
            for (int i = 0; i < 8; i++)
                #pragma unroll
                for (int j = 0; j < 8; j++) acc[i][j] += a[i]*b[j];
        }
        __syncthreads();
    }

    #pragma unroll
    for (int i = 0; i < 8; i++) {
        const int m = m0 + ty*8 + i;
        #pragma unroll
        for (int j = 0; j < 8; j++) {
            const int n = n0 + tx*8 + j;
            if (n < N)
                Co[(size_t)m*N + n] = fmaxf(acc[i][j] + bias[n], 0.f);
        }
    }
}

// ---------------- |h1 - h2| ----------------
__global__ void diff_kernel()
{
    int idx = blockIdx.x*blockDim.x + threadIdx.x;
    if (idx >= BATCH*1920) return;
    int b = idx / 1920;
    int r = idx % 1920;
    int t = r / 64, h = r % 64;
    float a = g_H3seq[((size_t)b*TT + t)*64 + h];
    float c = g_H3seq[((size_t)(b + BATCH)*TT + t)*64 + h];
    g_D[idx] = fabsf(a - c);
}

// ---------------- fused FC3 + FC4 head ----------------
__global__ __launch_bounds__(256) void head_kernel(const float* __restrict__ Wf3,
                                                   const float* __restrict__ bf3,
                                                   const float* __restrict__ Wf4,
                                                   const float* __restrict__ bf4,
                                                   float* __restrict__ out)
{
    __shared__ float w3[16*480];
    __shared__ float w4[16];
    __shared__ float b3s[16];
    for (int i = threadIdx.x; i < 16*480; i += blockDim.x) w3[i] = Wf3[i];
    if (threadIdx.x < 16) { w4[threadIdx.x] = Wf4[threadIdx.x]; b3s[threadIdx.x] = bf3[threadIdx.x]; }
    __syncthreads();

    int b = blockIdx.x*blockDim.x + threadIdx.x;
    if (b >= BATCH) return;

    float acc[16];
    #pragma unroll
    for (int j = 0; j < 16; j++) acc[j] = b3s[j];

    const float* __restrict__ row = g_F2 + (size_t)b*480;
    for (int k = 0; k < 480; k++) {
        float v = row[k];
        #pragma unroll
        for (int j = 0; j < 16; j++) acc[j] += v * w3[j*480 + k];
    }
    float o = bf4[0];
    #pragma unroll
    for (int j = 0; j < 16; j++) o += fmaxf(acc[j], 0.f) * w4[j];
    out[b] = o;
}

// ---------------- launch ----------------
static const int LSTM_DSMEM = 81920;  // 2 stages x 4 tiles x 128 x 20 words x 4 B

extern "C" void kernel_launch(void* const* d_in, const int* in_sizes, int n_in,
                              void* d_out, int out_size)
{
    const float* x1   = (const float*)d_in[0];
    const float* x2   = (const float*)d_in[1];
    const float* Wih1 = (const float*)d_in[2];
    const float* Whh1 = (const float*)d_in[3];
    const float* b1   = (const float*)d_in[4];
    const float* Wih2 = (const float*)d_in[5];
    const float* Whh2 = (const float*)d_in[6];
    const float* b2   = (const float*)d_in[7];
    const float* Wih3 = (const float*)d_in[8];
    const float* Whh3 = (const float*)d_in[9];
    const float* b3   = (const float*)d_in[10];
    const float* Wf1  = (const float*)d_in[11];
    const float* bf1  = (const float*)d_in[12];
    const float* Wf2  = (const float*)d_in[13];
    const float* bf2  = (const float*)d_in[14];
    const float* Wf3  = (const float*)d_in[15];
    const float* bf3  = (const float*)d_in[16];
    const float* Wf4  = (const float*)d_in[17];
    const float* bf4  = (const float*)d_in[18];
    float* out = (float*)d_out;

    cudaFuncSetAttribute(lstm_step<H1, 64, 1>, cudaFuncAttributeMaxDynamicSharedMemorySize, LSTM_DSMEM);
    cudaFuncSetAttribute(lstm_step<H2, H1, 2>, cudaFuncAttributeMaxDynamicSharedMemorySize, LSTM_DSMEM);
    cudaFuncSetAttribute(lstm_step<H3, H2, 3>, cudaFuncAttributeMaxDynamicSharedMemorySize, LSTM_DSMEM);

    pack_x_hilo<<<(BB*TT*64 + 255)/256, 256>>>(x1, x2);
    pack_wb<1><<<(2048*576 + 255)/256, 256>>>(Wih1, Whh1);
    pack_wb<2><<<(512*640  + 255)/256, 256>>>(Wih2, Whh2);
    pack_wb<3><<<(256*192  + 255)/256, 256>>>(Wih3, Whh3);
    pack_bias<<<(2816 + 255)/256, 256>>>(b1, b2, b3);
    pack_wf1<<<(1920*960 + 255)/256, 256>>>(Wf1);
    pack_wf2<<<(960*480  + 255)/256, 256>>>(Wf2);

    // layer 1: 58 -> 512   (KT = 576)
    zero_state<<<(BB*H1 + 255)/256, 256>>>();
    for (int t = 0; t < TT; t++)
        lstm_step<H1, 64, 1><<<dim3(BB/128, (4*H1)/128), 256, LSTM_DSMEM>>>(t);

    // layer 2: 512 -> 128  (KT = 640)
    zero_state<<<(BB*H1 + 255)/256, 256>>>();
    for (int t = 0; t < TT; t++)
        lstm_step<H2, H1, 2><<<dim3(BB/128, (4*H2)/128), 256, LSTM_DSMEM>>>(t);

    // layer 3: 128 -> 64   (KT = 192)
    zero_state<<<(BB*H1 + 255)/256, 256>>>();
    for (int t = 0; t < TT; t++)
        lstm_step<H3, H2, 3><<<dim3(BB/128, (4*H3)/128), 256, LSTM_DSMEM>>>(t);

    diff_kernel<<<(BATCH*1920 + 255)/256, 256>>>();

    fc_gemm<1><<<dim3(BATCH/128, (960 + 127)/128), 256>>>(bf1, BATCH, 960, 1920);
    fc_gemm<2><<<dim3(BATCH/128, (480 + 127)/128), 256>>>(bf2, BATCH, 480, 960);
    head_kernel<<<(BATCH + 255)/256, 256>>>(Wf3, bf3, Wf4, bf4, out);
}